// round 3
// baseline (speedup 1.0000x reference)
#include <cuda_runtime.h>
#include <math.h>

// PyTorchCG: BS=64, N=1024, maxiter derived from out_size.
#define CG_N  1024
#define CG_BS 64
#define TS    128                 // symmetric tile size
#define NT    (CG_N / TS)         // 8 tiles per dim
#define NPAIR (NT * (NT + 1) / 2) // 36 unique tile pairs

// Persistent CG state (no allocs allowed -> __device__ globals).
__device__ float g_r  [CG_BS * CG_N];
__device__ float g_p  [CG_BS * CG_N];
__device__ float g_Ap [CG_BS * CG_N];
__device__ float g_d  [CG_BS * CG_N];   // diag(M_inv)
__device__ float g_rz [CG_BS];
__device__ float g_pap[CG_BS];

// ---------------------------------------------------------------------------
// Zero accumulators before the first matvec.
// ---------------------------------------------------------------------------
__global__ void k_zero()
{
    const int b = blockIdx.x, tid = threadIdx.x;
    reinterpret_cast<float4*>(g_Ap + (size_t)b * CG_N)[tid] =
        make_float4(0.f, 0.f, 0.f, 0.f);
    if (tid == 0) g_pap[b] = 0.f;
}

// ---------------------------------------------------------------------------
// Symmetric batched matvec: g_Ap[b] += A[b] @ v[b] using A = A^T.
// CTA = one unique 128x128 tile pair (bi<=bj) per batch: 36*64 = 2304 CTAs.
// The load loop is 16 INDEPENDENT LDG.128 per warp with only FFMAs between
// (row-dot partials held in registers); every reduction happens post-loop.
// Off-diag tiles feed both y_bi (row dots) and y_bj (transpose col sums).
// Also accumulates p.Ap into g_pap[b].  v==nullptr -> use g_p.
// g_Ap / g_pap must be zero on entry.
// ---------------------------------------------------------------------------
__global__ void __launch_bounds__(256) k_symmv(const float* __restrict__ A,
                                               const float* __restrict__ v)
{
    const int b   = blockIdx.y;
    const int tid = threadIdx.x;

    // linear pair index -> (bi, bj), bi <= bj
    int li = blockIdx.x, bi = 0;
    while (li >= NT - bi) { li -= NT - bi; ++bi; }
    const int  bj   = bi + li;
    const bool diag = (bi == bj);

    __shared__ float spi[TS];            // v segment bi
    __shared__ float spj[TS];            // v segment bj
    __shared__ float sd[8][16][33];      // row-dot partials (padded, 16.9KB)
    __shared__ float scol[8][TS];        // col-sum partials
    __shared__ float sbuf[8];            // pap block reduce

    const float* vb = (v != nullptr) ? (v + (size_t)b * CG_N)
                                     : (g_p + (size_t)b * CG_N);
    if (tid < TS / 4)
        reinterpret_cast<float4*>(spi)[tid] =
            reinterpret_cast<const float4*>(vb + bi * TS)[tid];
    else if (tid < TS / 2)
        reinterpret_cast<float4*>(spj)[tid - TS / 4] =
            reinterpret_cast<const float4*>(vb + bj * TS)[tid - TS / 4];
    __syncthreads();

    const int warp = tid >> 5;
    const int lane = tid & 31;

    const float4* Abase = reinterpret_cast<const float4*>(
        A + ((size_t)b * CG_N + (size_t)bi * TS) * CG_N + (size_t)bj * TS);
    const int rstride = CG_N / 4;

    const float4 pj4 = reinterpret_cast<const float4*>(spj)[lane];

    // ---- pure load/FMA loop: 16 independent LDG.128, no reductions ----
    float  dpart[16];
    float4 cacc = make_float4(0.f, 0.f, 0.f, 0.f);
#pragma unroll
    for (int rr = 0; rr < 16; ++rr) {
        const int r = warp + 8 * rr;                 // row within tile
        float4 a = Abase[(size_t)r * rstride + lane];
        dpart[rr] = a.x * pj4.x + a.y * pj4.y + a.z * pj4.z + a.w * pj4.w;
        const float pir = spi[r];
        cacc.x += a.x * pir;  cacc.y += a.y * pir;
        cacc.z += a.z * pir;  cacc.w += a.w * pir;
    }

    // ---- post-loop reductions ----
#pragma unroll
    for (int rr = 0; rr < 16; ++rr)
        sd[warp][rr][lane] = dpart[rr];
    if (!diag) {                                     // uniform per CTA
        scol[warp][4 * lane + 0] = cacc.x;
        scol[warp][4 * lane + 1] = cacc.y;
        scol[warp][4 * lane + 2] = cacc.z;
        scol[warp][4 * lane + 3] = cacc.w;
    }
    __syncthreads();

    // row dots: thread pair (ri, hi) sums 16 of 32 partials, combine via shfl
    const int ri = tid >> 1;          // row 0..127
    const int hi = tid & 1;
    float s = 0.f;
#pragma unroll
    for (int j = 0; j < 16; ++j)
        s += sd[ri & 7][ri >> 3][16 * hi + j];
    s += __shfl_xor_sync(0xffffffffu, s, 1);

    float pap_c = 0.f;
    if (hi == 0) {
        atomicAdd(&g_Ap[(size_t)b * CG_N + (size_t)bi * TS + ri], s);
        pap_c = s * spi[ri];                         // p_i^T (T p_j) partial
    }

    // transpose part: column sums -> y_bj
    if (!diag && tid < TS) {
        float cs = 0.f;
#pragma unroll
        for (int w = 0; w < 8; ++w) cs += scol[w][tid];
        atomicAdd(&g_Ap[(size_t)b * CG_N + (size_t)bj * TS + tid], cs);
    }

    // pAp: block-reduce pap_c over all 256 threads (zeros where hi==1)
#pragma unroll
    for (int off = 16; off; off >>= 1)
        pap_c += __shfl_xor_sync(0xffffffffu, pap_c, off);
    if (lane == 0) sbuf[warp] = pap_c;
    __syncthreads();
    if (tid == 0) {
        float t = 0.f;
#pragma unroll
        for (int w = 0; w < 8; ++w) t += sbuf[w];
        atomicAdd(&g_pap[b], diag ? t : 2.f * t);
    }
}

// ---------------------------------------------------------------------------
// Deterministic block-wide sum over 256 threads.
// ---------------------------------------------------------------------------
__device__ __forceinline__ float block_sum(float v, float* sbuf)
{
    const int tid = threadIdx.x;
#pragma unroll
    for (int off = 16; off; off >>= 1)
        v += __shfl_xor_sync(0xffffffffu, v, off);
    if ((tid & 31) == 0) sbuf[tid >> 5] = v;
    __syncthreads();
    if (tid < 8) {
        float w = sbuf[tid];
#pragma unroll
        for (int off = 4; off; off >>= 1)
            w += __shfl_xor_sync(0x000000ffu, w, off);
        if (tid == 0) sbuf[0] = w;
    }
    __syncthreads();
    float r = sbuf[0];
    __syncthreads();
    return r;
}

// ---------------------------------------------------------------------------
// Init: diag extract, r0 = b - A@x0 (g_Ap), z0 = d*r0, p0 = z0, rz0, ||r0||.
// Re-zeroes g_Ap / g_pap for the first loop matvec.  grid=BS, block=256.
// ---------------------------------------------------------------------------
__global__ void k_init(const float* __restrict__ Minv,
                       const float* __restrict__ bvec,
                       float* __restrict__ out, int ldout)
{
    __shared__ float sbuf[8];
    const int b   = blockIdx.x;
    const int tid = threadIdx.x;
    const float* Mb = Minv + (size_t)b * CG_N * CG_N;

    float rz_p = 0.f, rr_p = 0.f;
#pragma unroll
    for (int k = 0; k < CG_N / 256; ++k) {
        const int    i  = tid + 256 * k;
        const size_t gi = (size_t)b * CG_N + i;
        float dv = Mb[(size_t)i * CG_N + i];
        float rv = bvec[gi] - g_Ap[gi];
        g_Ap[gi] = 0.f;
        float zv = dv * rv;
        g_d[gi] = dv;
        g_r[gi] = rv;
        g_p[gi] = zv;
        rz_p += rv * zv;
        rr_p += rv * rv;
    }
    float rz = block_sum(rz_p, sbuf);
    float rr = block_sum(rr_p, sbuf);
    if (tid == 0) {
        g_rz[b]  = rz;
        g_pap[b] = 0.f;
        out[(size_t)b * ldout] = sqrtf(rr);
    }
}

// ---------------------------------------------------------------------------
// CG update after g_Ap = A@p (g_pap = p.Ap from the matvec epilogue):
//   alpha = rz/pAp; r -= alpha*Ap; z = d*r; beta = rz_new/rz; p = z + beta*p.
// Zeroes g_Ap / g_pap in place for the next iteration.  grid=BS, block=256.
// ---------------------------------------------------------------------------
__global__ void k_update(float* __restrict__ out, int it, int ldout)
{
    __shared__ float sbuf[8];
    const int b   = blockIdx.x;
    const int tid = threadIdx.x;

    const float rz_old = g_rz[b];
    const float pAp    = g_pap[b];
    const float alpha  = rz_old / pAp;

    float pv[4], rv[4], dv[4];
    float rz_p = 0.f, rr_p = 0.f;
#pragma unroll
    for (int k = 0; k < 4; ++k) {
        const size_t i = (size_t)b * CG_N + tid + 256 * k;
        const float ap = g_Ap[i];
        g_Ap[i] = 0.f;
        pv[k] = g_p[i];
        dv[k] = g_d[i];
        rv[k] = g_r[i] - alpha * ap;
        g_r[i] = rv[k];
        const float zv = dv[k] * rv[k];
        rz_p += rv[k] * zv;
        rr_p += rv[k] * rv[k];
    }
    const float rz_new = block_sum(rz_p, sbuf);
    const float rr     = block_sum(rr_p, sbuf);
    const float beta   = rz_new / rz_old;

#pragma unroll
    for (int k = 0; k < 4; ++k) {
        const size_t i = (size_t)b * CG_N + tid + 256 * k;
        g_p[i] = dv[k] * rv[k] + beta * pv[k];
    }

    if (tid == 0) {
        g_rz[b]  = rz_new;
        g_pap[b] = 0.f;
        out[(size_t)b * ldout + it + 1] = sqrtf(rr);
    }
}

// ---------------------------------------------------------------------------
// kernel_launch: graph-capturable kernel sequence.
// ---------------------------------------------------------------------------
extern "C" void kernel_launch(void* const* d_in, const int* in_sizes, int n_in,
                              void* d_out, int out_size)
{
    const float* A    = (const float*)d_in[0];
    const float* bvec = (const float*)d_in[1];
    const float* x0   = (const float*)d_in[2];
    const float* Minv = (const float*)d_in[3];
    float* out        = (float*)d_out;

    const int ldout   = out_size / CG_BS;   // maxiter + 1
    const int maxiter = ldout - 1;

    dim3 grid_mv(NPAIR, CG_BS);             // 36 x 64 = 2304 CTAs

    k_zero<<<CG_BS, 256>>>();
    k_symmv<<<grid_mv, 256>>>(A, x0);       // g_Ap = A @ x0
    k_init <<<CG_BS, 256>>>(Minv, bvec, out, ldout);

    for (int it = 0; it < maxiter; ++it) {
        k_symmv<<<grid_mv, 256>>>(A, nullptr);   // g_Ap = A@p, g_pap = p.Ap
        k_update<<<CG_BS, 256>>>(out, it, ldout);
    }
}

// round 4
// speedup vs baseline: 1.5507x; 1.5507x over previous
#include <cuda_runtime.h>
#include <math.h>

// PyTorchCG: BS=64, N=1024, maxiter derived from out_size.
#define CG_N  1024
#define CG_BS 64
#define TS    128                 // symmetric tile size
#define NT    (CG_N / TS)         // 8 tiles per dim
#define NPAIR (NT * (NT + 1) / 2) // 36 unique tile pairs
#define TILE_F  (TS * TS)         // floats per packed tile
#define TILE_F4 (TILE_F / 4)

// Persistent CG state (no allocs allowed -> __device__ globals).
__device__ float g_r  [CG_BS * CG_N];
__device__ float g_p  [CG_BS * CG_N];
__device__ float g_Ap [CG_BS * CG_N];
__device__ float g_d  [CG_BS * CG_N];   // diag(M_inv)
__device__ float g_rz [CG_BS];
__device__ float g_pap[CG_BS];
// Packed upper-triangle tiles: [b][pair][128x128] contiguous (144 MB scratch).
__device__ __align__(16) float g_pack[(size_t)CG_BS * NPAIR * TILE_F];

__device__ __forceinline__ int tri_off(int bi)   // pairs before tile-row bi
{
    return bi * NT - (bi * (bi - 1)) / 2;
}

// ---------------------------------------------------------------------------
// Pack: copy upper-triangle tiles of A into contiguous per-tile storage.
// One warp per matrix row; reads are row-contiguous (streaming), writes are
// 512B-coalesced per tile chunk.  grid = (N/8, BS), block = 256.
// ---------------------------------------------------------------------------
__global__ void __launch_bounds__(256) k_pack(const float* __restrict__ A)
{
    const int b    = blockIdx.y;
    const int warp = threadIdx.x >> 5;
    const int lane = threadIdx.x & 31;
    const int row  = (blockIdx.x << 3) + warp;     // 0..1023
    const int bi   = row >> 7;
    const int rloc = row & (TS - 1);

    const float4* Arow =
        reinterpret_cast<const float4*>(A + ((size_t)b * CG_N + row) * CG_N);

    for (int k = bi; k < NT; ++k) {                // tile column bj = k
        float4 a = Arow[lane + 32 * k];
        const int li = tri_off(bi) + (k - bi);
        float4* dst = reinterpret_cast<float4*>(g_pack) +
                      ((size_t)b * NPAIR + li) * TILE_F4 + rloc * 32 + lane;
        *dst = a;
    }
}

// ---------------------------------------------------------------------------
// Zero accumulators before the first matvec.
// ---------------------------------------------------------------------------
__global__ void k_zero()
{
    const int b = blockIdx.x, tid = threadIdx.x;
    reinterpret_cast<float4*>(g_Ap + (size_t)b * CG_N)[tid] =
        make_float4(0.f, 0.f, 0.f, 0.f);
    if (tid == 0) g_pap[b] = 0.f;
}

// ---------------------------------------------------------------------------
// Symmetric batched matvec on PACKED tiles: g_Ap[b] += A[b] @ v[b], A = A^T.
// CTA = one tile pair (bi<=bj) per batch: 36*64 = 2304 CTAs.
// Each warp reads a CONTIGUOUS 8KB block (16 rows of the packed tile) as two
// 8-deep independent float4 batches; all reductions post-loop (smem).
// Off-diag tiles feed y_bi (row dots) and y_bj (transpose col sums).
// Accumulates p.Ap into g_pap[b].  v==nullptr -> use g_p.
// g_Ap / g_pap must be zero on entry.
// ---------------------------------------------------------------------------
__global__ void __launch_bounds__(256) k_symmv(const float* __restrict__ v)
{
    const int b   = blockIdx.y;
    const int tid = threadIdx.x;

    // linear pair index -> (bi, bj), bi <= bj
    int li = blockIdx.x, bi = 0;
    while (li >= NT - bi) { li -= NT - bi; ++bi; }
    const int  bj   = bi + li;
    const bool diag = (bi == bj);

    __shared__ float spi[TS];            // v segment bi
    __shared__ float spj[TS];            // v segment bj
    __shared__ float sd[8][16][33];      // row-dot partials (padded)
    __shared__ float scol[8][TS];        // col-sum partials
    __shared__ float sbuf[8];            // pap block reduce

    const float* vb = (v != nullptr) ? (v + (size_t)b * CG_N)
                                     : (g_p + (size_t)b * CG_N);
    if (tid < TS / 4)
        reinterpret_cast<float4*>(spi)[tid] =
            reinterpret_cast<const float4*>(vb + bi * TS)[tid];
    else if (tid < TS / 2)
        reinterpret_cast<float4*>(spj)[tid - TS / 4] =
            reinterpret_cast<const float4*>(vb + bj * TS)[tid - TS / 4];
    __syncthreads();

    const int warp = tid >> 5;
    const int lane = tid & 31;

    // warp's contiguous 16-row block of the packed tile
    const float4* T = reinterpret_cast<const float4*>(g_pack) +
                      ((size_t)b * NPAIR + blockIdx.x) * TILE_F4 +
                      (size_t)warp * 16 * 32;

    const float4 pj4 = reinterpret_cast<const float4*>(spj)[lane];
    float4 cacc = make_float4(0.f, 0.f, 0.f, 0.f);

    // ---- batch 0: rows 16w..16w+7, 8 independent contiguous LDG.128 ----
    {
        float4 a[8];
#pragma unroll
        for (int k = 0; k < 8; ++k) a[k] = T[k * 32 + lane];
#pragma unroll
        for (int k = 0; k < 8; ++k) {
            sd[warp][k][lane] = a[k].x * pj4.x + a[k].y * pj4.y +
                                a[k].z * pj4.z + a[k].w * pj4.w;
            const float pir = spi[16 * warp + k];
            cacc.x += a[k].x * pir;  cacc.y += a[k].y * pir;
            cacc.z += a[k].z * pir;  cacc.w += a[k].w * pir;
        }
    }
    // ---- batch 1: rows 16w+8..16w+15 ----
    {
        float4 a[8];
#pragma unroll
        for (int k = 0; k < 8; ++k) a[k] = T[(k + 8) * 32 + lane];
#pragma unroll
        for (int k = 0; k < 8; ++k) {
            sd[warp][k + 8][lane] = a[k].x * pj4.x + a[k].y * pj4.y +
                                    a[k].z * pj4.z + a[k].w * pj4.w;
            const float pir = spi[16 * warp + 8 + k];
            cacc.x += a[k].x * pir;  cacc.y += a[k].y * pir;
            cacc.z += a[k].z * pir;  cacc.w += a[k].w * pir;
        }
    }

    if (!diag) {                                   // uniform per CTA
        scol[warp][4 * lane + 0] = cacc.x;
        scol[warp][4 * lane + 1] = cacc.y;
        scol[warp][4 * lane + 2] = cacc.z;
        scol[warp][4 * lane + 3] = cacc.w;
    }
    __syncthreads();

    // row dots: thread pair (ri, hi); row ri handled by warp ri>>4, slot ri&15
    const int ri = tid >> 1;
    const int hi = tid & 1;
    float s = 0.f;
#pragma unroll
    for (int j = 0; j < 16; ++j)
        s += sd[ri >> 4][ri & 15][16 * hi + j];
    s += __shfl_xor_sync(0xffffffffu, s, 1);

    float pap_c = 0.f;
    if (hi == 0) {
        atomicAdd(&g_Ap[(size_t)b * CG_N + (size_t)bi * TS + ri], s);
        pap_c = s * spi[ri];
    }

    // transpose part: column sums -> y_bj
    if (!diag && tid < TS) {
        float cs = 0.f;
#pragma unroll
        for (int w = 0; w < 8; ++w) cs += scol[w][tid];
        atomicAdd(&g_Ap[(size_t)b * CG_N + (size_t)bj * TS + tid], cs);
    }

    // pAp: block reduce (zeros where hi==1)
#pragma unroll
    for (int off = 16; off; off >>= 1)
        pap_c += __shfl_xor_sync(0xffffffffu, pap_c, off);
    if (lane == 0) sbuf[warp] = pap_c;
    __syncthreads();
    if (tid == 0) {
        float t = 0.f;
#pragma unroll
        for (int w = 0; w < 8; ++w) t += sbuf[w];
        atomicAdd(&g_pap[b], diag ? t : 2.f * t);
    }
}

// ---------------------------------------------------------------------------
// Deterministic block-wide sum over 256 threads.
// ---------------------------------------------------------------------------
__device__ __forceinline__ float block_sum(float v, float* sbuf)
{
    const int tid = threadIdx.x;
#pragma unroll
    for (int off = 16; off; off >>= 1)
        v += __shfl_xor_sync(0xffffffffu, v, off);
    if ((tid & 31) == 0) sbuf[tid >> 5] = v;
    __syncthreads();
    if (tid < 8) {
        float w = sbuf[tid];
#pragma unroll
        for (int off = 4; off; off >>= 1)
            w += __shfl_xor_sync(0x000000ffu, w, off);
        if (tid == 0) sbuf[0] = w;
    }
    __syncthreads();
    float r = sbuf[0];
    __syncthreads();
    return r;
}

// ---------------------------------------------------------------------------
// Init: diag extract, r0 = b - A@x0 (g_Ap), z0 = d*r0, p0 = z0, rz0, ||r0||.
// Re-zeroes g_Ap / g_pap for the first loop matvec.  grid=BS, block=256.
// ---------------------------------------------------------------------------
__global__ void k_init(const float* __restrict__ Minv,
                       const float* __restrict__ bvec,
                       float* __restrict__ out, int ldout)
{
    __shared__ float sbuf[8];
    const int b   = blockIdx.x;
    const int tid = threadIdx.x;
    const float* Mb = Minv + (size_t)b * CG_N * CG_N;

    float rz_p = 0.f, rr_p = 0.f;
#pragma unroll
    for (int k = 0; k < CG_N / 256; ++k) {
        const int    i  = tid + 256 * k;
        const size_t gi = (size_t)b * CG_N + i;
        float dv = Mb[(size_t)i * CG_N + i];
        float rv = bvec[gi] - g_Ap[gi];
        g_Ap[gi] = 0.f;
        float zv = dv * rv;
        g_d[gi] = dv;
        g_r[gi] = rv;
        g_p[gi] = zv;
        rz_p += rv * zv;
        rr_p += rv * rv;
    }
    float rz = block_sum(rz_p, sbuf);
    float rr = block_sum(rr_p, sbuf);
    if (tid == 0) {
        g_rz[b]  = rz;
        g_pap[b] = 0.f;
        out[(size_t)b * ldout] = sqrtf(rr);
    }
}

// ---------------------------------------------------------------------------
// CG update after g_Ap = A@p (g_pap = p.Ap from the matvec epilogue):
//   alpha = rz/pAp; r -= alpha*Ap; z = d*r; beta = rz_new/rz; p = z + beta*p.
// Zeroes g_Ap / g_pap in place for the next iteration.  grid=BS, block=256.
// ---------------------------------------------------------------------------
__global__ void k_update(float* __restrict__ out, int it, int ldout)
{
    __shared__ float sbuf[8];
    const int b   = blockIdx.x;
    const int tid = threadIdx.x;

    const float rz_old = g_rz[b];
    const float pAp    = g_pap[b];
    const float alpha  = rz_old / pAp;

    float pv[4], rv[4], dv[4];
    float rz_p = 0.f, rr_p = 0.f;
#pragma unroll
    for (int k = 0; k < 4; ++k) {
        const size_t i = (size_t)b * CG_N + tid + 256 * k;
        const float ap = g_Ap[i];
        g_Ap[i] = 0.f;
        pv[k] = g_p[i];
        dv[k] = g_d[i];
        rv[k] = g_r[i] - alpha * ap;
        g_r[i] = rv[k];
        const float zv = dv[k] * rv[k];
        rz_p += rv[k] * zv;
        rr_p += rv[k] * rv[k];
    }
    const float rz_new = block_sum(rz_p, sbuf);
    const float rr     = block_sum(rr_p, sbuf);
    const float beta   = rz_new / rz_old;

#pragma unroll
    for (int k = 0; k < 4; ++k) {
        const size_t i = (size_t)b * CG_N + tid + 256 * k;
        g_p[i] = dv[k] * rv[k] + beta * pv[k];
    }

    if (tid == 0) {
        g_rz[b]  = rz_new;
        g_pap[b] = 0.f;
        out[(size_t)b * ldout + it + 1] = sqrtf(rr);
    }
}

// ---------------------------------------------------------------------------
// kernel_launch: graph-capturable kernel sequence.
// ---------------------------------------------------------------------------
extern "C" void kernel_launch(void* const* d_in, const int* in_sizes, int n_in,
                              void* d_out, int out_size)
{
    const float* A    = (const float*)d_in[0];
    const float* bvec = (const float*)d_in[1];
    const float* x0   = (const float*)d_in[2];
    const float* Minv = (const float*)d_in[3];
    float* out        = (float*)d_out;

    const int ldout   = out_size / CG_BS;   // maxiter + 1
    const int maxiter = ldout - 1;

    dim3 grid_pk(CG_N / 8, CG_BS);          // pack: warp per row
    dim3 grid_mv(NPAIR, CG_BS);             // 36 x 64 = 2304 CTAs

    k_pack<<<grid_pk, 256>>>(A);            // one-time tile packing
    k_zero<<<CG_BS, 256>>>();
    k_symmv<<<grid_mv, 256>>>(x0);          // g_Ap = A @ x0
    k_init <<<CG_BS, 256>>>(Minv, bvec, out, ldout);

    for (int it = 0; it < maxiter; ++it) {
        k_symmv<<<grid_mv, 256>>>(nullptr);     // g_Ap = A@p, g_pap = p.Ap
        k_update<<<CG_BS, 256>>>(out, it, ldout);
    }
}